// round 13
// baseline (speedup 1.0000x reference)
#include <cuda_runtime.h>
#include <cuda_fp16.h>
#include <math.h>

// Problem constants
#define T_SEQ 2048
#define H_DIM 2048
#define NH 32
#define NKV 8
#define HD 64
#define SW 128
#define QM 4              // NH / NKV
#define QKVD 3072         // HD*(NH+2*NKV)
#define EPS 1e-5f

typedef unsigned short ushort_t;

// Scratch (device globals; no allocation allowed)
__device__ float g_qkv[T_SEQ * QKVD];
__device__ ushort_t g_nh[T_SEQ * H_DIM];       // rmsnorm out, fp16
__device__ ushort_t g_ah[T_SEQ * H_DIM];       // attn out, fp16
__device__ ushort_t g_wqkv[QKVD * H_DIM];      // qkv weight, [N][K] fp16
__device__ ushort_t g_wout[H_DIM * H_DIM];     // out weight, [N][K] fp16

__device__ __forceinline__ ushort_t hf_bits(float x) {
    __half h = __float2half_rn(x);
    return *reinterpret_cast<ushort_t*>(&h);
}
__device__ __forceinline__ unsigned packh2(float a, float b) {
    __half2 h = __floats2half2_rn(a, b);
    return *reinterpret_cast<unsigned*>(&h);
}

// ---------------------------------------------------------------------------
// Kernel 0: weight transpose + fp16 convert.  W[K][N] fp32 -> W[N][K] fp16
// ---------------------------------------------------------------------------
__global__ void split_transpose(const float* __restrict__ W,
                                ushort_t* __restrict__ Wh, int K, int N) {
    __shared__ float t[32][33];
    int n0 = blockIdx.x * 32, k0 = blockIdx.y * 32;
    int tx = threadIdx.x, ty = threadIdx.y;  // 32 x 8
#pragma unroll
    for (int i = 0; i < 4; i++)
        t[ty + i * 8][tx] = W[(size_t)(k0 + ty + i * 8) * N + n0 + tx];
    __syncthreads();
#pragma unroll
    for (int i = 0; i < 4; i++) {
        int n = ty + i * 8;
        Wh[(size_t)(n0 + n) * K + k0 + tx] = hf_bits(t[tx][n]);
    }
}

// ---------------------------------------------------------------------------
// Kernel 1: RMSNorm per row, emits fp16
// ---------------------------------------------------------------------------
__global__ void rmsnorm_kernel(const float* __restrict__ x,
                               const float* __restrict__ scale,
                               ushort_t* __restrict__ oh) {
    __shared__ float red[256];
    int row = blockIdx.x;
    int tid = threadIdx.x;
    const float4* xr = (const float4*)(x + (size_t)row * H_DIM);
    float4 v0 = xr[tid];
    float4 v1 = xr[tid + 256];
    float ss = v0.x * v0.x + v0.y * v0.y + v0.z * v0.z + v0.w * v0.w
             + v1.x * v1.x + v1.y * v1.y + v1.z * v1.z + v1.w * v1.w;
    red[tid] = ss;
    __syncthreads();
    for (int s = 128; s > 0; s >>= 1) {
        if (tid < s) red[tid] += red[tid + s];
        __syncthreads();
    }
    float inv = rsqrtf(red[0] * (1.0f / H_DIM) + EPS);
    const float4* sc = (const float4*)scale;
    float4 s0 = sc[tid], s1 = sc[tid + 256];
    float o[8];
    o[0] = v0.x * inv * s0.x; o[1] = v0.y * inv * s0.y;
    o[2] = v0.z * inv * s0.z; o[3] = v0.w * inv * s0.w;
    o[4] = v1.x * inv * s1.x; o[5] = v1.y * inv * s1.y;
    o[6] = v1.z * inv * s1.z; o[7] = v1.w * inv * s1.w;
    ushort_t h[8];
#pragma unroll
    for (int i = 0; i < 8; i++) h[i] = hf_bits(o[i]);
    size_t base = (size_t)row * H_DIM;
    *(uint2*)&oh[base + tid * 4] =
        make_uint2((unsigned)h[0] | ((unsigned)h[1] << 16),
                   (unsigned)h[2] | ((unsigned)h[3] << 16));
    *(uint2*)&oh[base + 1024 + tid * 4] =
        make_uint2((unsigned)h[4] | ((unsigned)h[5] << 16),
                   (unsigned)h[6] | ((unsigned)h[7] << 16));
}

// ---------------------------------------------------------------------------
// mma / ldmatrix helpers
// ---------------------------------------------------------------------------
__device__ __forceinline__ void mma16816(float* c, const unsigned* a, const unsigned* b) {
    asm volatile(
        "mma.sync.aligned.m16n8k16.row.col.f32.f16.f16.f32 "
        "{%0,%1,%2,%3}, {%4,%5,%6,%7}, {%8,%9}, {%0,%1,%2,%3};\n"
        : "+f"(c[0]), "+f"(c[1]), "+f"(c[2]), "+f"(c[3])
        : "r"(a[0]), "r"(a[1]), "r"(a[2]), "r"(a[3]), "r"(b[0]), "r"(b[1]));
}
__device__ __forceinline__ void ldsm4(unsigned* r, unsigned addr) {
    asm volatile("ldmatrix.sync.aligned.m8n8.x4.shared.b16 {%0,%1,%2,%3}, [%4];\n"
                 : "=r"(r[0]), "=r"(r[1]), "=r"(r[2]), "=r"(r[3]) : "r"(addr));
}
__device__ __forceinline__ void ldsm4t(unsigned* r, unsigned addr) {
    asm volatile("ldmatrix.sync.aligned.m8n8.x4.trans.shared.b16 {%0,%1,%2,%3}, [%4];\n"
                 : "=r"(r[0]), "=r"(r[1]), "=r"(r[2]), "=r"(r[3]) : "r"(addr));
}

// ---------------------------------------------------------------------------
// Tensor-core fp16 GEMM: C = A @ B^T + bias (+resid)
// ---------------------------------------------------------------------------
#define PAD 40
#define ARR_BYTES (128 * PAD * 2)
#define STAGE_BYTES (2 * ARR_BYTES)
#define GEMM_SMEM_BYTES (2 * STAGE_BYTES)

#define CP16(dst_u32, src_ptr) \
    asm volatile("cp.async.cg.shared.global [%0], [%1], 16;\n" \
                 :: "r"(dst_u32), "l"(src_ptr))

template <bool RESID>
__global__ __launch_bounds__(512, 2)
void gemm_mma(const ushort_t* __restrict__ A, const ushort_t* __restrict__ B,
              const float* __restrict__ bias, const float* __restrict__ resid,
              float* __restrict__ C, int M, int N, int K) {
    extern __shared__ ushort_t smem[];
    unsigned smem_u32 = (unsigned)__cvta_generic_to_shared((void*)smem);

    int tid = threadIdx.x;
    int lane = tid & 31;
    int wid = tid >> 5;
    int warp_m = wid & 7;
    int warp_n = wid >> 3;
    int row0 = blockIdx.y * 128;
    int col0 = blockIdx.x * 128;
    int m0 = warp_m * 16;
    int nb = warp_n * 64;

    float acc[8][4];
#pragma unroll
    for (int j = 0; j < 8; j++)
#pragma unroll
        for (int l = 0; l < 4; l++) acc[j][l] = 0.0f;

    unsigned offA = (unsigned)(((m0 + (lane & 15)) * PAD + (lane >> 4) * 8) * 2);
    unsigned offB = (unsigned)(((nb + (lane & 7) + ((lane >> 4) << 3)) * PAD
                                + ((lane >> 3) & 1) * 8) * 2);

    int r_ld = tid >> 2;
    int c8 = (tid & 3) * 8;
    unsigned soff = (unsigned)((r_ld * PAD + c8) * 2);

    int T = K / 32;
#pragma unroll 1
    for (int t = 0; t < T + 1; t++) {
        if (t < T) {
            int k0 = t * 32;
            unsigned sbase = smem_u32 + (t & 1) * STAGE_BYTES;
            size_t ga = (size_t)(row0 + r_ld) * K + k0 + c8;
            size_t gb = (size_t)(col0 + r_ld) * K + k0 + c8;
            CP16(sbase + soff, A + ga);
            CP16(sbase + ARR_BYTES + soff, B + gb);
            asm volatile("cp.async.commit_group;\n");
        }
        if (t == 0) continue;
        if (t < T) asm volatile("cp.async.wait_group 1;\n");
        else       asm volatile("cp.async.wait_group 0;\n");
        __syncthreads();

        unsigned sbase = smem_u32 + ((t - 1) & 1) * STAGE_BYTES;
#pragma unroll
        for (int ks = 0; ks < 2; ks++) {
            unsigned ksb = ks * 32;
            unsigned a[4];
            ldsm4(a, sbase + offA + ksb);
#pragma unroll
            for (int g = 0; g < 4; g++) {
                unsigned b[4];
                unsigned go = (unsigned)(g * 16 * PAD * 2);
                ldsm4(b, sbase + ARR_BYTES + offB + go + ksb);
                mma16816(acc[g * 2],     a, b);
                mma16816(acc[g * 2 + 1], a, b + 2);
            }
        }
        __syncthreads();
    }

    int r0 = row0 + m0 + (lane >> 2);
    int r1 = r0 + 8;
#pragma unroll
    for (int nh = 0; nh < 8; nh++) {
        int cc = col0 + nb + nh * 8 + (lane & 3) * 2;
        float b0 = bias[cc], b1 = bias[cc + 1];
        float2 v0, v1;
        v0.x = acc[nh][0] + b0; v0.y = acc[nh][1] + b1;
        v1.x = acc[nh][2] + b0; v1.y = acc[nh][3] + b1;
        if (RESID) {
            float2 rs0 = *(const float2*)&resid[(size_t)r0 * N + cc];
            float2 rs1 = *(const float2*)&resid[(size_t)r1 * N + cc];
            v0.x += rs0.x; v0.y += rs0.y;
            v1.x += rs1.x; v1.y += rs1.y;
        }
        *(float2*)&C[(size_t)r0 * N + cc] = v0;
        *(float2*)&C[(size_t)r1 * N + cc] = v1;
    }
}

// ---------------------------------------------------------------------------
// Kernel 3: RoPE in place on q (heads 0..31) and k (heads 32..39)
// ---------------------------------------------------------------------------
__global__ void rope_kernel(const float* __restrict__ cosT,
                            const float* __restrict__ sinT) {
    int idx = blockIdx.x * blockDim.x + threadIdx.x;
    if (idx >= T_SEQ * 40 * 32) return;
    int d = idx & 31;
    int rest = idx >> 5;
    int head = rest % 40;
    int t = rest / 40;
    float c = cosT[t * 32 + d];
    float s = sinT[t * 32 + d];
    float* p = g_qkv + (size_t)t * QKVD + head * 64 + d;
    float x1 = p[0];
    float x2 = p[32];
    p[0] = x1 * c - x2 * s;
    p[32] = x2 * c + x1 * s;
}

// ---------------------------------------------------------------------------
// Kernel 4: tensor-core sliding-window GQA attention with sinks.
// Block = 16 queries x 1 kv head (64 rows = 4 q-heads x 16q). 256 threads.
// Warp (w) = m-tile (w>>1) x key-half (w&1): half0 keys 0-63, half1 keys 64-143.
// QK^T and PV via m16n8k16 fp16 mma; S lives in registers.
// ---------------------------------------------------------------------------
#define ASTR 72
#define QOFF (64 * ASTR)                       // Ks start (halves)
#define VOFF (QOFF + 144 * ASTR)               // Vs start (halves)
#define STATB ((VOFF + 144 * ASTR) * 2)        // stats byte offset
#define ATT_SMEM (STATB + 2 * 128 * 4)         // 51712 B

__global__ __launch_bounds__(256, 2)
void attn_kernel(const float* __restrict__ sinks) {
    extern __shared__ __half smh[];
    unsigned smem_u32 = (unsigned)__cvta_generic_to_shared((void*)smh);
    float* maxbuf = (float*)((char*)smh + STATB);
    float* sumbuf = maxbuf + 128;
    float* Obuf = (float*)(smh + QOFF);        // alias Ks: [64][66] fp32

    int qb = blockIdx.x, n = blockIdx.y;
    int qstart = qb * 16;
    int kmin = qstart - SW; if (kmin < 0) kmin = 0;
    int tid = threadIdx.x;
    int lane = tid & 31, wid = tid >> 5;
    int mt = wid >> 1, half = wid & 1;
    int keybase = half * 64;
    int NT = half ? 10 : 8;    // QK n8-tiles for this warp
    int KT = half ? 5 : 4;     // PV k16-tiles

    // ---- load Q (x0.125), K, V as fp16 ----
#pragma unroll
    for (int i = 0; i < 8; i++) {
        int idx = tid + i * 256;
        int row = idx >> 5, col = (idx & 31) * 2;
        int m = row >> 4, qi = row & 15;
        float2 q = *(const float2*)&g_qkv[(size_t)(qstart + qi) * QKVD + n * 256 + m * 64 + col];
        *(__half2*)&smh[row * ASTR + col] = __floats2half2_rn(q.x * 0.125f, q.y * 0.125f);
    }
#pragma unroll
    for (int i = 0; i < 18; i++) {
        int idx = tid + i * 256;
        int r = idx >> 5, col = (idx & 31) * 2;
        float2 kk = *(const float2*)&g_qkv[(size_t)(kmin + r) * QKVD + 2048 + n * 64 + col];
        *(__half2*)&smh[QOFF + r * ASTR + col] = __floats2half2_rn(kk.x, kk.y);
        float2 vv = *(const float2*)&g_qkv[(size_t)(kmin + r) * QKVD + 2560 + n * 64 + col];
        *(__half2*)&smh[VOFF + r * ASTR + col] = __floats2half2_rn(vv.x, vv.y);
    }
    __syncthreads();

    // ---- QK^T ----
    float s[10][4];
#pragma unroll
    for (int j = 0; j < 10; j++)
#pragma unroll
        for (int l = 0; l < 4; l++) s[j][l] = 0.0f;

    unsigned offA = smem_u32 + (unsigned)(((mt * 16 + (lane & 15)) * ASTR + (lane >> 4) * 8) * 2);
    int brow = (lane & 7) + ((lane >> 4) << 3);
    int bko = ((lane >> 3) & 1) * 8;
#pragma unroll
    for (int ks = 0; ks < 4; ks++) {
        unsigned a[4];
        ldsm4(a, offA + ks * 32);
#pragma unroll
        for (int p = 0; p < 5; p++) {
            if (2 * p >= NT) break;
            unsigned b[4];
            unsigned addrB = smem_u32 +
                (unsigned)((QOFF + (keybase + p * 16 + brow) * ASTR + ks * 16 + bko) * 2);
            ldsm4(b, addrB);
            mma16816(s[2 * p], a, b);
            mma16816(s[2 * p + 1], a, b + 2);
        }
    }
    __syncthreads();   // Ks dead; Obuf (alias) safe after this point

    // ---- mask + row max ----
    int g = lane >> 2, t = lane & 3;
    int qg0 = qstart + g, qg1 = qg0 + 8;
    float m0 = -1e30f, m1 = -1e30f;
#pragma unroll
    for (int j = 0; j < 10; j++) {
        if (j >= NT) break;
        int k0 = kmin + keybase + j * 8 + t * 2;
        int k1 = k0 + 1;
        if (!(k0 <= qg0 && qg0 - k0 <= SW)) s[j][0] = -1e30f;
        if (!(k1 <= qg0 && qg0 - k1 <= SW)) s[j][1] = -1e30f;
        if (!(k0 <= qg1 && qg1 - k0 <= SW)) s[j][2] = -1e30f;
        if (!(k1 <= qg1 && qg1 - k1 <= SW)) s[j][3] = -1e30f;
        m0 = fmaxf(m0, fmaxf(s[j][0], s[j][1]));
        m1 = fmaxf(m1, fmaxf(s[j][2], s[j][3]));
    }
    m0 = fmaxf(m0, __shfl_xor_sync(0xffffffffu, m0, 1));
    m0 = fmaxf(m0, __shfl_xor_sync(0xffffffffu, m0, 2));
    m1 = fmaxf(m1, __shfl_xor_sync(0xffffffffu, m1, 1));
    m1 = fmaxf(m1, __shfl_xor_sync(0xffffffffu, m1, 2));
    if (t == 0) {
        maxbuf[(mt * 2 + half) * 16 + g] = m0;
        maxbuf[(mt * 2 + half) * 16 + g + 8] = m1;
    }
    __syncthreads();

    float snk = sinks[n * QM + mt];
    float M0 = fmaxf(fmaxf(maxbuf[(mt * 2) * 16 + g], maxbuf[(mt * 2 + 1) * 16 + g]), snk);
    float M1 = fmaxf(fmaxf(maxbuf[(mt * 2) * 16 + g + 8], maxbuf[(mt * 2 + 1) * 16 + g + 8]), snk);

    // ---- exp + row sum (P kept unnormalized in regs) ----
    float sum0 = 0.0f, sum1 = 0.0f;
#pragma unroll
    for (int j = 0; j < 10; j++) {
        if (j >= NT) break;
        s[j][0] = __expf(s[j][0] - M0);
        s[j][1] = __expf(s[j][1] - M0);
        s[j][2] = __expf(s[j][2] - M1);
        s[j][3] = __expf(s[j][3] - M1);
        sum0 += s[j][0] + s[j][1];
        sum1 += s[j][2] + s[j][3];
    }
    sum0 += __shfl_xor_sync(0xffffffffu, sum0, 1);
    sum0 += __shfl_xor_sync(0xffffffffu, sum0, 2);
    sum1 += __shfl_xor_sync(0xffffffffu, sum1, 1);
    sum1 += __shfl_xor_sync(0xffffffffu, sum1, 2);
    if (t == 0) {
        sumbuf[(mt * 2 + half) * 16 + g] = sum0;
        sumbuf[(mt * 2 + half) * 16 + g + 8] = sum1;
    }
    __syncthreads();

    float inv0 = 1.0f / (sumbuf[(mt * 2) * 16 + g] + sumbuf[(mt * 2 + 1) * 16 + g]
                         + __expf(snk - M0));
    float inv1 = 1.0f / (sumbuf[(mt * 2) * 16 + g + 8] + sumbuf[(mt * 2 + 1) * 16 + g + 8]
                         + __expf(snk - M1));

    // ---- PV: O += P @ V ----
    float o[8][4];
#pragma unroll
    for (int j = 0; j < 8; j++)
#pragma unroll
        for (int l = 0; l < 4; l++) o[j][l] = 0.0f;

    int vrow_lane = lane & 15;
    int vcol_lane = (lane >> 4) * 8;
#pragma unroll
    for (int kt = 0; kt < 5; kt++) {
        if (kt >= KT) break;
        unsigned a[4];
        a[0] = packh2(s[2 * kt][0], s[2 * kt][1]);
        a[1] = packh2(s[2 * kt][2], s[2 * kt][3]);
        a[2] = packh2(s[2 * kt + 1][0], s[2 * kt + 1][1]);
        a[3] = packh2(s[2 * kt + 1][2], s[2 * kt + 1][3]);
#pragma unroll
        for (int jd = 0; jd < 4; jd++) {
            unsigned b[4];
            unsigned addrV = smem_u32 +
                (unsigned)((VOFF + (keybase + kt * 16 + vrow_lane) * ASTR
                            + jd * 16 + vcol_lane) * 2);
            ldsm4t(b, addrV);
            mma16816(o[2 * jd], a, b);
            mma16816(o[2 * jd + 1], a, b + 2);
        }
    }

    // ---- combine halves via Obuf, normalize, store fp16 ----
    if (half == 1) {
#pragma unroll
        for (int jd = 0; jd < 8; jd++) {
            int col = jd * 8 + t * 2;
            *(float2*)&Obuf[(mt * 16 + g) * 66 + col] = make_float2(o[jd][0], o[jd][1]);
            *(float2*)&Obuf[(mt * 16 + g + 8) * 66 + col] = make_float2(o[jd][2], o[jd][3]);
        }
    }
    __syncthreads();
    if (half == 0) {
#pragma unroll
        for (int jd = 0; jd < 8; jd++) {
            int col = jd * 8 + t * 2;
            float2 p0 = *(float2*)&Obuf[(mt * 16 + g) * 66 + col];
            float2 p1 = *(float2*)&Obuf[(mt * 16 + g + 8) * 66 + col];
            float v00 = (o[jd][0] + p0.x) * inv0;
            float v01 = (o[jd][1] + p0.y) * inv0;
            float v10 = (o[jd][2] + p1.x) * inv1;
            float v11 = (o[jd][3] + p1.y) * inv1;
            size_t c0 = (size_t)(qstart + g) * H_DIM + n * 256 + mt * 64 + col;
            size_t c1 = (size_t)(qstart + g + 8) * H_DIM + n * 256 + mt * 64 + col;
            *(unsigned*)&g_ah[c0] = packh2(v00, v01);
            *(unsigned*)&g_ah[c1] = packh2(v10, v11);
        }
    }
}

// ---------------------------------------------------------------------------
// Launch
// ---------------------------------------------------------------------------
extern "C" void kernel_launch(void* const* d_in, const int* in_sizes, int n_in,
                              void* d_out, int out_size) {
    const float* x       = (const float*)d_in[0];
    const float* scale   = (const float*)d_in[1];
    const float* sinks   = (const float*)d_in[2];
    const float* qkvW    = (const float*)d_in[3];
    const float* qkvB    = (const float*)d_in[4];
    const float* outW    = (const float*)d_in[5];
    const float* outB    = (const float*)d_in[6];
    const float* cosT    = (const float*)d_in[7];
    const float* sinT    = (const float*)d_in[8];
    float* out = (float*)d_out;

    ushort_t *p_nh, *p_ah, *p_wqkv, *p_wout;
    cudaGetSymbolAddress((void**)&p_nh, g_nh);
    cudaGetSymbolAddress((void**)&p_ah, g_ah);
    cudaGetSymbolAddress((void**)&p_wqkv, g_wqkv);
    cudaGetSymbolAddress((void**)&p_wout, g_wout);
    float* p_qkv;
    cudaGetSymbolAddress((void**)&p_qkv, g_qkv);

    // 0. transpose + fp16 weights
    {
        dim3 blk(32, 8);
        split_transpose<<<dim3(QKVD / 32, H_DIM / 32), blk>>>(qkvW, p_wqkv, H_DIM, QKVD);
        split_transpose<<<dim3(H_DIM / 32, H_DIM / 32), blk>>>(outW, p_wout, H_DIM, H_DIM);
    }

    // 1. RMSNorm -> fp16
    rmsnorm_kernel<<<T_SEQ, 256>>>(x, scale, p_nh);

    // 2. QKV GEMM
    {
        cudaFuncSetAttribute(gemm_mma<false>, cudaFuncAttributeMaxDynamicSharedMemorySize,
                             GEMM_SMEM_BYTES);
        dim3 grid(QKVD / 128, T_SEQ / 128);
        gemm_mma<false><<<grid, 512, GEMM_SMEM_BYTES>>>(p_nh, p_wqkv,
                                                        qkvB, nullptr, p_qkv,
                                                        T_SEQ, QKVD, H_DIM);
    }

    // 3. RoPE on q + k
    {
        int total = T_SEQ * 40 * 32;
        rope_kernel<<<(total + 255) / 256, 256>>>(cosT, sinT);
    }

    // 4. Attention (tensor cores) -> fp16
    {
        cudaFuncSetAttribute(attn_kernel, cudaFuncAttributeMaxDynamicSharedMemorySize,
                             ATT_SMEM);
        dim3 grid(T_SEQ / 16, NKV);
        attn_kernel<<<grid, 256, ATT_SMEM>>>(sinks);
    }

    // 5. Output projection + residual
    {
        cudaFuncSetAttribute(gemm_mma<true>, cudaFuncAttributeMaxDynamicSharedMemorySize,
                             GEMM_SMEM_BYTES);
        dim3 grid(H_DIM / 128, T_SEQ / 128);
        gemm_mma<true><<<grid, 512, GEMM_SMEM_BYTES>>>(p_ah, p_wout,
                                                       outB, x, out,
                                                       T_SEQ, H_DIM, H_DIM);
    }
}

// round 15
// speedup vs baseline: 1.5271x; 1.5271x over previous
#include <cuda_runtime.h>
#include <cuda_fp16.h>
#include <math.h>

// Problem constants
#define T_SEQ 2048
#define H_DIM 2048
#define NH 32
#define NKV 8
#define HD 64
#define SW 128
#define QM 4              // NH / NKV
#define QKVD 3072         // HD*(NH+2*NKV)
#define EPS 1e-5f

typedef unsigned short ushort_t;

// Scratch (device globals; no allocation allowed)
__device__ float g_qkv[T_SEQ * QKVD];
__device__ ushort_t g_nh[T_SEQ * H_DIM];       // rmsnorm out, fp16
__device__ ushort_t g_ah[T_SEQ * H_DIM];       // attn out, fp16
__device__ ushort_t g_wqkv[QKVD * H_DIM];      // qkv weight, [N][K] fp16
__device__ ushort_t g_wout[H_DIM * H_DIM];     // out weight, [N][K] fp16

__device__ __forceinline__ ushort_t hf_bits(float x) {
    __half h = __float2half_rn(x);
    return *reinterpret_cast<ushort_t*>(&h);
}
__device__ __forceinline__ unsigned packh2(float a, float b) {
    __half2 h = __floats2half2_rn(a, b);
    return *reinterpret_cast<unsigned*>(&h);
}

// ---------------------------------------------------------------------------
// Kernel 0: weight transpose + fp16 convert.  W[K][N] fp32 -> W[N][K] fp16
// ---------------------------------------------------------------------------
__global__ void split_transpose(const float* __restrict__ W,
                                ushort_t* __restrict__ Wh, int K, int N) {
    __shared__ float t[32][33];
    int n0 = blockIdx.x * 32, k0 = blockIdx.y * 32;
    int tx = threadIdx.x, ty = threadIdx.y;  // 32 x 8
#pragma unroll
    for (int i = 0; i < 4; i++)
        t[ty + i * 8][tx] = W[(size_t)(k0 + ty + i * 8) * N + n0 + tx];
    __syncthreads();
#pragma unroll
    for (int i = 0; i < 4; i++) {
        int n = ty + i * 8;
        Wh[(size_t)(n0 + n) * K + k0 + tx] = hf_bits(t[tx][n]);
    }
}

// ---------------------------------------------------------------------------
// Kernel 1: RMSNorm per row, emits fp16
// ---------------------------------------------------------------------------
__global__ void rmsnorm_kernel(const float* __restrict__ x,
                               const float* __restrict__ scale,
                               ushort_t* __restrict__ oh) {
    __shared__ float red[256];
    int row = blockIdx.x;
    int tid = threadIdx.x;
    const float4* xr = (const float4*)(x + (size_t)row * H_DIM);
    float4 v0 = xr[tid];
    float4 v1 = xr[tid + 256];
    float ss = v0.x * v0.x + v0.y * v0.y + v0.z * v0.z + v0.w * v0.w
             + v1.x * v1.x + v1.y * v1.y + v1.z * v1.z + v1.w * v1.w;
    red[tid] = ss;
    __syncthreads();
    for (int s = 128; s > 0; s >>= 1) {
        if (tid < s) red[tid] += red[tid + s];
        __syncthreads();
    }
    float inv = rsqrtf(red[0] * (1.0f / H_DIM) + EPS);
    const float4* sc = (const float4*)scale;
    float4 s0 = sc[tid], s1 = sc[tid + 256];
    float o[8];
    o[0] = v0.x * inv * s0.x; o[1] = v0.y * inv * s0.y;
    o[2] = v0.z * inv * s0.z; o[3] = v0.w * inv * s0.w;
    o[4] = v1.x * inv * s1.x; o[5] = v1.y * inv * s1.y;
    o[6] = v1.z * inv * s1.z; o[7] = v1.w * inv * s1.w;
    ushort_t h[8];
#pragma unroll
    for (int i = 0; i < 8; i++) h[i] = hf_bits(o[i]);
    size_t base = (size_t)row * H_DIM;
    *(uint2*)&oh[base + tid * 4] =
        make_uint2((unsigned)h[0] | ((unsigned)h[1] << 16),
                   (unsigned)h[2] | ((unsigned)h[3] << 16));
    *(uint2*)&oh[base + 1024 + tid * 4] =
        make_uint2((unsigned)h[4] | ((unsigned)h[5] << 16),
                   (unsigned)h[6] | ((unsigned)h[7] << 16));
}

// ---------------------------------------------------------------------------
// mma / ldmatrix helpers
// ---------------------------------------------------------------------------
__device__ __forceinline__ void mma16816(float* c, const unsigned* a, const unsigned* b) {
    asm volatile(
        "mma.sync.aligned.m16n8k16.row.col.f32.f16.f16.f32 "
        "{%0,%1,%2,%3}, {%4,%5,%6,%7}, {%8,%9}, {%0,%1,%2,%3};\n"
        : "+f"(c[0]), "+f"(c[1]), "+f"(c[2]), "+f"(c[3])
        : "r"(a[0]), "r"(a[1]), "r"(a[2]), "r"(a[3]), "r"(b[0]), "r"(b[1]));
}
__device__ __forceinline__ void ldsm4(unsigned* r, unsigned addr) {
    asm volatile("ldmatrix.sync.aligned.m8n8.x4.shared.b16 {%0,%1,%2,%3}, [%4];\n"
                 : "=r"(r[0]), "=r"(r[1]), "=r"(r[2]), "=r"(r[3]) : "r"(addr));
}
__device__ __forceinline__ void ldsm4t(unsigned* r, unsigned addr) {
    asm volatile("ldmatrix.sync.aligned.m8n8.x4.trans.shared.b16 {%0,%1,%2,%3}, [%4];\n"
                 : "=r"(r[0]), "=r"(r[1]), "=r"(r[2]), "=r"(r[3]) : "r"(addr));
}

// ---------------------------------------------------------------------------
// Tensor-core fp16 GEMM: C = A @ B^T + bias (+resid)
// ---------------------------------------------------------------------------
#define PAD 40
#define ARR_BYTES (128 * PAD * 2)
#define STAGE_BYTES (2 * ARR_BYTES)
#define GEMM_SMEM_BYTES (2 * STAGE_BYTES)

#define CP16(dst_u32, src_ptr) \
    asm volatile("cp.async.cg.shared.global [%0], [%1], 16;\n" \
                 :: "r"(dst_u32), "l"(src_ptr))

template <bool RESID>
__global__ __launch_bounds__(512, 2)
void gemm_mma(const ushort_t* __restrict__ A, const ushort_t* __restrict__ B,
              const float* __restrict__ bias, const float* __restrict__ resid,
              float* __restrict__ C, int M, int N, int K) {
    extern __shared__ ushort_t smem[];
    unsigned smem_u32 = (unsigned)__cvta_generic_to_shared((void*)smem);

    int tid = threadIdx.x;
    int lane = tid & 31;
    int wid = tid >> 5;
    int warp_m = wid & 7;
    int warp_n = wid >> 3;
    int row0 = blockIdx.y * 128;
    int col0 = blockIdx.x * 128;
    int m0 = warp_m * 16;
    int nb = warp_n * 64;

    float acc[8][4];
#pragma unroll
    for (int j = 0; j < 8; j++)
#pragma unroll
        for (int l = 0; l < 4; l++) acc[j][l] = 0.0f;

    unsigned offA = (unsigned)(((m0 + (lane & 15)) * PAD + (lane >> 4) * 8) * 2);
    unsigned offB = (unsigned)(((nb + (lane & 7) + ((lane >> 4) << 3)) * PAD
                                + ((lane >> 3) & 1) * 8) * 2);

    int r_ld = tid >> 2;
    int c8 = (tid & 3) * 8;
    unsigned soff = (unsigned)((r_ld * PAD + c8) * 2);

    int T = K / 32;
#pragma unroll 1
    for (int t = 0; t < T + 1; t++) {
        if (t < T) {
            int k0 = t * 32;
            unsigned sbase = smem_u32 + (t & 1) * STAGE_BYTES;
            size_t ga = (size_t)(row0 + r_ld) * K + k0 + c8;
            size_t gb = (size_t)(col0 + r_ld) * K + k0 + c8;
            CP16(sbase + soff, A + ga);
            CP16(sbase + ARR_BYTES + soff, B + gb);
            asm volatile("cp.async.commit_group;\n");
        }
        if (t == 0) continue;
        if (t < T) asm volatile("cp.async.wait_group 1;\n");
        else       asm volatile("cp.async.wait_group 0;\n");
        __syncthreads();

        unsigned sbase = smem_u32 + ((t - 1) & 1) * STAGE_BYTES;
#pragma unroll
        for (int ks = 0; ks < 2; ks++) {
            unsigned ksb = ks * 32;
            unsigned a[4];
            ldsm4(a, sbase + offA + ksb);
#pragma unroll
            for (int g = 0; g < 4; g++) {
                unsigned b[4];
                unsigned go = (unsigned)(g * 16 * PAD * 2);
                ldsm4(b, sbase + ARR_BYTES + offB + go + ksb);
                mma16816(acc[g * 2],     a, b);
                mma16816(acc[g * 2 + 1], a, b + 2);
            }
        }
        __syncthreads();
    }

    int r0 = row0 + m0 + (lane >> 2);
    int r1 = r0 + 8;
#pragma unroll
    for (int nh = 0; nh < 8; nh++) {
        int cc = col0 + nb + nh * 8 + (lane & 3) * 2;
        float b0 = bias[cc], b1 = bias[cc + 1];
        float2 v0, v1;
        v0.x = acc[nh][0] + b0; v0.y = acc[nh][1] + b1;
        v1.x = acc[nh][2] + b0; v1.y = acc[nh][3] + b1;
        if (RESID) {
            float2 rs0 = *(const float2*)&resid[(size_t)r0 * N + cc];
            float2 rs1 = *(const float2*)&resid[(size_t)r1 * N + cc];
            v0.x += rs0.x; v0.y += rs0.y;
            v1.x += rs1.x; v1.y += rs1.y;
        }
        *(float2*)&C[(size_t)r0 * N + cc] = v0;
        *(float2*)&C[(size_t)r1 * N + cc] = v1;
    }
}

// ---------------------------------------------------------------------------
// Kernel 3: RoPE in place on q (heads 0..31) and k (heads 32..39)
// ---------------------------------------------------------------------------
__global__ void rope_kernel(const float* __restrict__ cosT,
                            const float* __restrict__ sinT) {
    int idx = blockIdx.x * blockDim.x + threadIdx.x;
    if (idx >= T_SEQ * 40 * 32) return;
    int d = idx & 31;
    int rest = idx >> 5;
    int head = rest % 40;
    int t = rest / 40;
    float c = cosT[t * 32 + d];
    float s = sinT[t * 32 + d];
    float* p = g_qkv + (size_t)t * QKVD + head * 64 + d;
    float x1 = p[0];
    float x2 = p[32];
    p[0] = x1 * c - x2 * s;
    p[32] = x2 * c + x1 * s;
}

// ---------------------------------------------------------------------------
// Kernel 4: tensor-core sliding-window GQA attention with sinks.
// Block = 16 queries x 1 kv head (64 rows = 4 q-heads x 16q). 256 threads.
// Warp (w) = m-tile (w>>1) x key-half (w&1): half0 keys 0-63, half1 keys 64-143.
// QK^T and PV via m16n8k16 fp16 mma; S lives in registers.
// ---------------------------------------------------------------------------
#define ASTR 72
#define QOFF (64 * ASTR)                       // Ks start (halves)
#define VOFF (QOFF + 144 * ASTR)               // Vs start (halves)
#define STATB ((VOFF + 144 * ASTR) * 2)        // stats byte offset
#define ATT_SMEM (STATB + 2 * 128 * 4)         // 51712 B

__global__ __launch_bounds__(256, 2)
void attn_kernel(const float* __restrict__ sinks) {
    extern __shared__ __half smh[];
    unsigned smem_u32 = (unsigned)__cvta_generic_to_shared((void*)smh);
    float* maxbuf = (float*)((char*)smh + STATB);
    float* sumbuf = maxbuf + 128;
    float* Obuf = (float*)(smh + QOFF);        // alias Ks: [64][66] fp32

    int qb = blockIdx.x, n = blockIdx.y;
    int qstart = qb * 16;
    int kmin = qstart - SW; if (kmin < 0) kmin = 0;
    int tid = threadIdx.x;
    int lane = tid & 31, wid = tid >> 5;
    int mt = wid >> 1, half = wid & 1;
    int keybase = half * 64;
    int NT = half ? 10 : 8;    // QK n8-tiles for this warp
    int KT = half ? 5 : 4;     // PV k16-tiles

    // ---- load Q (x0.125), K, V as fp16 ----
#pragma unroll
    for (int i = 0; i < 8; i++) {
        int idx = tid + i * 256;
        int row = idx >> 5, col = (idx & 31) * 2;
        int m = row >> 4, qi = row & 15;
        float2 q = *(const float2*)&g_qkv[(size_t)(qstart + qi) * QKVD + n * 256 + m * 64 + col];
        *(__half2*)&smh[row * ASTR + col] = __floats2half2_rn(q.x * 0.125f, q.y * 0.125f);
    }
#pragma unroll
    for (int i = 0; i < 18; i++) {
        int idx = tid + i * 256;
        int r = idx >> 5, col = (idx & 31) * 2;
        float2 kk = *(const float2*)&g_qkv[(size_t)(kmin + r) * QKVD + 2048 + n * 64 + col];
        *(__half2*)&smh[QOFF + r * ASTR + col] = __floats2half2_rn(kk.x, kk.y);
        float2 vv = *(const float2*)&g_qkv[(size_t)(kmin + r) * QKVD + 2560 + n * 64 + col];
        *(__half2*)&smh[VOFF + r * ASTR + col] = __floats2half2_rn(vv.x, vv.y);
    }
    __syncthreads();

    // ---- QK^T ----
    float s[10][4];
#pragma unroll
    for (int j = 0; j < 10; j++)
#pragma unroll
        for (int l = 0; l < 4; l++) s[j][l] = 0.0f;

    unsigned offA = smem_u32 + (unsigned)(((mt * 16 + (lane & 15)) * ASTR + (lane >> 4) * 8) * 2);
    int brow = (lane & 7) + ((lane >> 4) << 3);
    int bko = ((lane >> 3) & 1) * 8;
#pragma unroll
    for (int ks = 0; ks < 4; ks++) {
        unsigned a[4];
        ldsm4(a, offA + ks * 32);
#pragma unroll
        for (int p = 0; p < 5; p++) {
            if (2 * p >= NT) break;
            unsigned b[4];
            unsigned addrB = smem_u32 +
                (unsigned)((QOFF + (keybase + p * 16 + brow) * ASTR + ks * 16 + bko) * 2);
            ldsm4(b, addrB);
            mma16816(s[2 * p], a, b);
            mma16816(s[2 * p + 1], a, b + 2);
        }
    }
    __syncthreads();   // Ks dead; Obuf (alias) safe after this point

    // ---- mask + row max ----
    int g = lane >> 2, t = lane & 3;
    int qg0 = qstart + g, qg1 = qg0 + 8;
    float m0 = -1e30f, m1 = -1e30f;
#pragma unroll
    for (int j = 0; j < 10; j++) {
        if (j >= NT) break;
        int k0 = kmin + keybase + j * 8 + t * 2;
        int k1 = k0 + 1;
        if (!(k0 <= qg0 && qg0 - k0 <= SW)) s[j][0] = -1e30f;
        if (!(k1 <= qg0 && qg0 - k1 <= SW)) s[j][1] = -1e30f;
        if (!(k0 <= qg1 && qg1 - k0 <= SW)) s[j][2] = -1e30f;
        if (!(k1 <= qg1 && qg1 - k1 <= SW)) s[j][3] = -1e30f;
        m0 = fmaxf(m0, fmaxf(s[j][0], s[j][1]));
        m1 = fmaxf(m1, fmaxf(s[j][2], s[j][3]));
    }
    m0 = fmaxf(m0, __shfl_xor_sync(0xffffffffu, m0, 1));
    m0 = fmaxf(m0, __shfl_xor_sync(0xffffffffu, m0, 2));
    m1 = fmaxf(m1, __shfl_xor_sync(0xffffffffu, m1, 1));
    m1 = fmaxf(m1, __shfl_xor_sync(0xffffffffu, m1, 2));
    if (t == 0) {
        maxbuf[(mt * 2 + half) * 16 + g] = m0;
        maxbuf[(mt * 2 + half) * 16 + g + 8] = m1;
    }
    __syncthreads();

    float snk = sinks[n * QM + mt];
    float M0 = fmaxf(fmaxf(maxbuf[(mt * 2) * 16 + g], maxbuf[(mt * 2 + 1) * 16 + g]), snk);
    float M1 = fmaxf(fmaxf(maxbuf[(mt * 2) * 16 + g + 8], maxbuf[(mt * 2 + 1) * 16 + g + 8]), snk);

    // ---- exp + row sum (P kept unnormalized in regs) ----
    float sum0 = 0.0f, sum1 = 0.0f;
#pragma unroll
    for (int j = 0; j < 10; j++) {
        if (j >= NT) break;
        s[j][0] = __expf(s[j][0] - M0);
        s[j][1] = __expf(s[j][1] - M0);
        s[j][2] = __expf(s[j][2] - M1);
        s[j][3] = __expf(s[j][3] - M1);
        sum0 += s[j][0] + s[j][1];
        sum1 += s[j][2] + s[j][3];
    }
    sum0 += __shfl_xor_sync(0xffffffffu, sum0, 1);
    sum0 += __shfl_xor_sync(0xffffffffu, sum0, 2);
    sum1 += __shfl_xor_sync(0xffffffffu, sum1, 1);
    sum1 += __shfl_xor_sync(0xffffffffu, sum1, 2);
    if (t == 0) {
        sumbuf[(mt * 2 + half) * 16 + g] = sum0;
        sumbuf[(mt * 2 + half) * 16 + g + 8] = sum1;
    }
    __syncthreads();

    float inv0 = 1.0f / (sumbuf[(mt * 2) * 16 + g] + sumbuf[(mt * 2 + 1) * 16 + g]
                         + __expf(snk - M0));
    float inv1 = 1.0f / (sumbuf[(mt * 2) * 16 + g + 8] + sumbuf[(mt * 2 + 1) * 16 + g + 8]
                         + __expf(snk - M1));

    // ---- PV: O += P @ V ----
    float o[8][4];
#pragma unroll
    for (int j = 0; j < 8; j++)
#pragma unroll
        for (int l = 0; l < 4; l++) o[j][l] = 0.0f;

    int vrow_lane = lane & 15;
    int vcol_lane = (lane >> 4) * 8;
#pragma unroll
    for (int kt = 0; kt < 5; kt++) {
        if (kt >= KT) break;
        unsigned a[4];
        a[0] = packh2(s[2 * kt][0], s[2 * kt][1]);
        a[1] = packh2(s[2 * kt][2], s[2 * kt][3]);
        a[2] = packh2(s[2 * kt + 1][0], s[2 * kt + 1][1]);
        a[3] = packh2(s[2 * kt + 1][2], s[2 * kt + 1][3]);
#pragma unroll
        for (int jd = 0; jd < 4; jd++) {
            unsigned b[4];
            unsigned addrV = smem_u32 +
                (unsigned)((VOFF + (keybase + kt * 16 + vrow_lane) * ASTR
                            + jd * 16 + vcol_lane) * 2);
            ldsm4t(b, addrV);
            mma16816(o[2 * jd], a, b);
            mma16816(o[2 * jd + 1], a, b + 2);
        }
    }

    // ---- combine halves via Obuf, normalize, store fp16 ----
    if (half == 1) {
#pragma unroll
        for (int jd = 0; jd < 8; jd++) {
            int col = jd * 8 + t * 2;
            *(float2*)&Obuf[(mt * 16 + g) * 66 + col] = make_float2(o[jd][0], o[jd][1]);
            *(float2*)&Obuf[(mt * 16 + g + 8) * 66 + col] = make_float2(o[jd][2], o[jd][3]);
        }
    }
    __syncthreads();
    if (half == 0) {
#pragma unroll
        for (int jd = 0; jd < 8; jd++) {
            int col = jd * 8 + t * 2;
            float2 p0 = *(float2*)&Obuf[(mt * 16 + g) * 66 + col];
            float2 p1 = *(float2*)&Obuf[(mt * 16 + g + 8) * 66 + col];
            float v00 = (o[jd][0] + p0.x) * inv0;
            float v01 = (o[jd][1] + p0.y) * inv0;
            float v10 = (o[jd][2] + p1.x) * inv1;
            float v11 = (o[jd][3] + p1.y) * inv1;
            size_t c0 = (size_t)(qstart + g) * H_DIM + n * 256 + mt * 64 + col;
            size_t c1 = (size_t)(qstart + g + 8) * H_DIM + n * 256 + mt * 64 + col;
            *(unsigned*)&g_ah[c0] = packh2(v00, v01);
            *(unsigned*)&g_ah[c1] = packh2(v10, v11);
        }
    }
}

// ---------------------------------------------------------------------------
// Launch
// ---------------------------------------------------------------------------
extern "C" void kernel_launch(void* const* d_in, const int* in_sizes, int n_in,
                              void* d_out, int out_size) {
    const float* x       = (const float*)d_in[0];
    const float* scale   = (const float*)d_in[1];
    const float* sinks   = (const float*)d_in[2];
    const float* qkvW    = (const float*)d_in[3];
    const float* qkvB    = (const float*)d_in[4];
    const float* outW    = (const float*)d_in[5];
    const float* outB    = (const float*)d_in[6];
    const float* cosT    = (const float*)d_in[7];
    const float* sinT    = (const float*)d_in[8];
    float* out = (float*)d_out;

    ushort_t *p_nh, *p_ah, *p_wqkv, *p_wout;
    cudaGetSymbolAddress((void**)&p_nh, g_nh);
    cudaGetSymbolAddress((void**)&p_ah, g_ah);
    cudaGetSymbolAddress((void**)&p_wqkv, g_wqkv);
    cudaGetSymbolAddress((void**)&p_wout, g_wout);
    float* p_qkv;
    cudaGetSymbolAddress((void**)&p_qkv, g_qkv);

    // 0. transpose + fp16 weights
    {
        dim3 blk(32, 8);
        split_transpose<<<dim3(QKVD / 32, H_DIM / 32), blk>>>(qkvW, p_wqkv, H_DIM, QKVD);
        split_transpose<<<dim3(H_DIM / 32, H_DIM / 32), blk>>>(outW, p_wout, H_DIM, H_DIM);
    }

    // 1. RMSNorm -> fp16
    rmsnorm_kernel<<<T_SEQ, 256>>>(x, scale, p_nh);

    // 2. QKV GEMM
    {
        cudaFuncSetAttribute(gemm_mma<false>, cudaFuncAttributeMaxDynamicSharedMemorySize,
                             GEMM_SMEM_BYTES);
        dim3 grid(QKVD / 128, T_SEQ / 128);
        gemm_mma<false><<<grid, 512, GEMM_SMEM_BYTES>>>(p_nh, p_wqkv,
                                                        qkvB, nullptr, p_qkv,
                                                        T_SEQ, QKVD, H_DIM);
    }

    // 3. RoPE on q + k
    {
        int total = T_SEQ * 40 * 32;
        rope_kernel<<<(total + 255) / 256, 256>>>(cosT, sinT);
    }

    // 4. Attention (tensor cores) -> fp16
    {
        cudaFuncSetAttribute(attn_kernel, cudaFuncAttributeMaxDynamicSharedMemorySize,
                             ATT_SMEM);
        dim3 grid(T_SEQ / 16, NKV);
        attn_kernel<<<grid, 256, ATT_SMEM>>>(sinks);
    }

    // 5. Output projection + residual
    {
        cudaFuncSetAttribute(gemm_mma<true>, cudaFuncAttributeMaxDynamicSharedMemorySize,
                             GEMM_SMEM_BYTES);
        dim3 grid(H_DIM / 128, T_SEQ / 128);
        gemm_mma<true><<<grid, 512, GEMM_SMEM_BYTES>>>(p_ah, p_wout,
                                                       outB, x, out,
                                                       T_SEQ, H_DIM, H_DIM);
    }
}